// round 12
// baseline (speedup 1.0000x reference)
#include <cuda_runtime.h>
#include <cstdint>

// x: [B=16, C=8, T=262144] fp32 row-major.
// out = x * (c == 0 ? 1.0f : 0.5f)
//
// Block-independence probe: 8192 blocks x 512 threads, contiguous 16 KB
// tiles, exactly ONE 256-bit load+store per thread. Completes the controlled
// block-count curve (592 -> 69.8%, 2048 -> 72.7%, 4096 -> 75.3%, 8192 -> ?).
//
// Units: float8 (32 B). Tile = 512 vec8 = 16 KB. Channel row = 32768 vec8
// = 64 tiles, so channel is uniform per block:
//   channel = (blockIdx.x >> 6) & 7.

static constexpr long long N_VEC8  = (16LL * 8LL * 262144LL) / 8;  // 4,194,304
static constexpr int       THREADS = 512;
static constexpr int       TILE    = THREADS;                      // 512 vec8 = 16 KB
static constexpr int       BLOCKS  = (int)(N_VEC8 / TILE);         // 8192, exact

struct alignas(32) f8 { float v[8]; };

__device__ __forceinline__ f8 ldg256(const f8* p) {
    f8 r;
    asm volatile(
        "ld.global.nc.v8.f32 {%0, %1, %2, %3, %4, %5, %6, %7}, [%8];"
        : "=f"(r.v[0]), "=f"(r.v[1]), "=f"(r.v[2]), "=f"(r.v[3]),
          "=f"(r.v[4]), "=f"(r.v[5]), "=f"(r.v[6]), "=f"(r.v[7])
        : "l"(p));
    return r;
}

__device__ __forceinline__ void stg256(f8* p, const f8& r) {
    asm volatile(
        "st.global.v8.f32 [%0], {%1, %2, %3, %4, %5, %6, %7, %8};"
        :: "l"(p),
           "f"(r.v[0]), "f"(r.v[1]), "f"(r.v[2]), "f"(r.v[3]),
           "f"(r.v[4]), "f"(r.v[5]), "f"(r.v[6]), "f"(r.v[7])
        : "memory");
}

__global__ void __launch_bounds__(THREADS) channel_scale_kernel(
    const f8* __restrict__ x, f8* __restrict__ out)
{
    // Per-block uniform channel scale: channel = (blockIdx.x >> 6) & 7.
    const float s = ((blockIdx.x & (7u << 6)) == 0u) ? 1.0f : 0.5f;

    const long long i = (long long)blockIdx.x * TILE + threadIdx.x;

    f8 a = ldg256(&x[i]);
#pragma unroll
    for (int j = 0; j < 8; j++) a.v[j] *= s;
    stg256(&out[i], a);
}

extern "C" void kernel_launch(void* const* d_in, const int* in_sizes, int n_in,
                              void* d_out, int out_size)
{
    const f8* x = (const f8*)d_in[0];
    f8* out = (f8*)d_out;
    channel_scale_kernel<<<BLOCKS, THREADS>>>(x, out);
}